// round 13
// baseline (speedup 1.0000x reference)
#include <cuda_runtime.h>
#include <cstdint>

#define HH 2048
#define WW 2048
#define NB 148
#define NT 1024
#define NW 32
#define CBLK 74
#define TOT4 (HH*WW/4)          // 1,048,576 float4 per channel
#define STR (CBLK*NT)           // 75,776
#define CSZ 8                   // band cluster size

// Only cross-kernel state: phase-0 block partials, fully rewritten each launch.
__device__ float4 g_p0[NB];

__device__ __forceinline__ float neg_inf() { return __int_as_float(0xff800000); }
__device__ __forceinline__ float fmax4(float4 A) {
    return fmaxf(fmaxf(A.x, A.y), fmaxf(A.z, A.w));
}

// ---- cluster / mbarrier helpers ----
__device__ __forceinline__ uint32_t smem_u32(const void *p) {
    return (uint32_t)__cvta_generic_to_shared(p);
}
__device__ __forceinline__ uint32_t mapa_u32(uint32_t a, uint32_t rank) {
    uint32_t r;
    asm volatile("mapa.shared::cluster.u32 %0, %1, %2;" : "=r"(r) : "r"(a), "r"(rank));
    return r;
}
__device__ __forceinline__ void st_clu_b64(uint32_t a, uint64_t v) {
    asm volatile("st.shared::cluster.b64 [%0], %1;" :: "r"(a), "l"(v) : "memory");
}
__device__ __forceinline__ void mbar_init(uint32_t a, unsigned cnt) {
    asm volatile("mbarrier.init.shared.b64 [%0], %1;" :: "r"(a), "r"(cnt) : "memory");
}
__device__ __forceinline__ void mbar_inval(uint32_t a) {
    asm volatile("mbarrier.inval.shared.b64 [%0];" :: "r"(a) : "memory");
}
__device__ __forceinline__ void mbar_arrive_remote(uint32_t a) {
    asm volatile("mbarrier.arrive.release.cluster.shared::cluster.b64 _, [%0];" :: "r"(a) : "memory");
}
__device__ __forceinline__ void mbar_wait(uint32_t a, unsigned parity) {
    asm volatile(
        "{\n\t.reg .pred P;\n\t"
        "W_%=:\n\t"
        "mbarrier.try_wait.parity.acquire.cluster.shared::cta.b64 P, [%0], %1, 0x989680;\n\t"
        "@P bra.uni D_%=;\n\t"
        "bra.uni W_%=;\n\t"
        "D_%=:\n\t}"
        :: "r"(a), "r"(parity) : "memory");
}
__device__ __forceinline__ uint64_t pack2(float a, float b) {
    uint64_t d;
    asm("mov.b64 %0, {%1, %2};" : "=l"(d) : "r"(__float_as_uint(a)), "r"(__float_as_uint(b)));
    return d;
}
#define CLUSTER_BAR() do { \
    asm volatile("barrier.cluster.arrive.aligned;" ::: "memory"); \
    asm volatile("barrier.cluster.wait.aligned;"   ::: "memory"); \
} while (0)

// Block-wide max, broadcast to ALL threads (3 bars; used outside band loop).
__device__ float block_max_bcast(float m) {
    __shared__ float sm[NW];
    __shared__ float sM;
    int tid = threadIdx.x;
    __syncthreads();
    #pragma unroll
    for (int o = 16; o; o >>= 1) m = fmaxf(m, __shfl_xor_sync(0xffffffffu, m, o));
    if ((tid & 31) == 0) sm[tid >> 5] = m;
    __syncthreads();
    if (tid < 32) {
        float t = sm[tid];
        #pragma unroll
        for (int o = 16; o; o >>= 1) t = fmaxf(t, __shfl_xor_sync(0xffffffffu, t, o));
        if (tid == 0) sM = t;
    }
    __syncthreads();
    return sM;
}

// Block-wide 3-way sum; result valid on threads 0..31.
__device__ void block_sum3(float &S, float &Sx, float &Sy) {
    __shared__ float ss[NW][3];
    int tid = threadIdx.x;
    __syncthreads();
    #pragma unroll
    for (int o = 16; o; o >>= 1) {
        S  += __shfl_xor_sync(0xffffffffu, S, o);
        Sx += __shfl_xor_sync(0xffffffffu, Sx, o);
        Sy += __shfl_xor_sync(0xffffffffu, Sy, o);
    }
    if ((tid & 31) == 0) { ss[tid >> 5][0] = S; ss[tid >> 5][1] = Sx; ss[tid >> 5][2] = Sy; }
    __syncthreads();
    if (tid < 32) {
        S = ss[tid][0]; Sx = ss[tid][1]; Sy = ss[tid][2];
        #pragma unroll
        for (int o = 16; o; o >>= 1) {
            S  += __shfl_xor_sync(0xffffffffu, S, o);
            Sx += __shfl_xor_sync(0xffffffffu, Sx, o);
            Sy += __shfl_xor_sync(0xffffffffu, Sy, o);
        }
    }
}

// Fixed-max accumulate (phase0 reload). Ms is the SCALED (x100) block max.
__device__ __forceinline__ void accf(float Ms, float &S, float &Sx, float &Sy,
                                     float raw, float x, float y) {
    float v = raw * 100.f;
    if (v > Ms - 88.f) {
        float e = expf(v - Ms);
        S += e; Sx += x * e; Sy += y * e;
    }
}

// ================= Kernel A: phase-0 streaming (148 blocks, no sync) =================
__global__ void __launch_bounds__(NT, 1)
phase0_kernel(const float * __restrict__ hm) {
    const int b = blockIdx.x;
    const int tid = threadIdx.x;
    const int c  = (b < CBLK) ? 0 : 1;
    const int bb = (b < CBLK) ? b : b - CBLK;
    const float4 *p4 = reinterpret_cast<const float4*>(hm + (size_t)(9 + c) * HH * WW);
    const int ibase = bb * NT + tid;

    // pass A: branch-free RAW max, tile maxima kept in regs
    float bmx[4];
    #pragma unroll
    for (int k = 0; k < 3; k++) {
        float4 A = p4[ibase + (4*k + 0) * STR];
        float4 B = p4[ibase + (4*k + 1) * STR];
        float4 C = p4[ibase + (4*k + 2) * STR];
        float4 D = p4[ibase + (4*k + 3) * STR];
        bmx[k] = fmaxf(fmaxf(fmax4(A), fmax4(B)), fmaxf(fmax4(C), fmax4(D)));
    }
    {
        float4 A = p4[ibase + 12 * STR];
        float m3 = fmax4(A);
        int i13 = ibase + 13 * STR;
        if (i13 < TOT4) { float4 B = p4[i13]; m3 = fmaxf(m3, fmax4(B)); }
        bmx[3] = m3;
    }
    float Mb = block_max_bcast(fmaxf(fmaxf(bmx[0], bmx[1]), fmaxf(bmx[2], bmx[3])));

    // pass B: ballot-skip reload of qualifying tiles (L2 hits), sums rel. BLOCK max
    const float Ms     = Mb * 100.f;
    const float thrRaw = Mb - 0.88f;
    float S = 0.f, Sx = 0.f, Sy = 0.f;
    #pragma unroll
    for (int k = 0; k < 4; k++) {
        if (__any_sync(0xffffffffu, bmx[k] > thrRaw)) {
            int tlo = 4 * k, thi = (k == 3) ? 14 : 4 * k + 4;
            for (int t = tlo; t < thi; t++) {
                int idx = ibase + t * STR;
                if (idx < TOT4) {
                    float4 A = p4[idx];
                    float y  = (float)(idx >> 9);
                    float x0 = (float)((idx & 511) << 2);
                    accf(Ms, S, Sx, Sy, A.x, x0,       y);
                    accf(Ms, S, Sx, Sy, A.y, x0 + 1.f, y);
                    accf(Ms, S, Sx, Sy, A.z, x0 + 2.f, y);
                    accf(Ms, S, Sx, Sy, A.w, x0 + 3.f, y);
                }
            }
        }
    }
    block_sum3(S, Sx, Sy);
    if (tid == 0) g_p0[b] = make_float4(Mb, S, Sx, Sy);   // RAW max + relative sums
}

// 2-bar CTA max broadcast (dedicated smem)
__device__ __forceinline__ float cmax2(float m) {
    __shared__ float sWm[NW];
    __shared__ float sMx;
    int tid = threadIdx.x;
    #pragma unroll
    for (int o = 16; o; o >>= 1) m = fmaxf(m, __shfl_xor_sync(0xffffffffu, m, o));
    if ((tid & 31) == 0) sWm[tid >> 5] = m;
    __syncthreads();
    if (tid < 32) {
        float t = sWm[tid];
        #pragma unroll
        for (int o = 16; o; o >>= 1) t = fmaxf(t, __shfl_xor_sync(0xffffffffu, t, o));
        if (tid == 0) sMx = t;
    }
    __syncthreads();
    return sMx;
}

// ============ Kernel B: finisher + 9 band phases, ONE 8-CTA cluster ============
__global__ void __launch_bounds__(NT, 1) __cluster_dims__(CSZ, 1, 1)
bands_kernel(const float * __restrict__ hm, float * __restrict__ out) {
    const int b = blockIdx.x;           // == cluster rank (single cluster)
    const int tid = threadIdx.x;
    const int lane = tid & 31;
    const int w = tid >> 5;
    __shared__ float s_ay, s_ay2[2];
    __shared__ float sRed[NW][3];
    __shared__ __align__(16) float4 s_all[2][CSZ];   // pushed partials, parity-buffered
    __shared__ __align__(8)  uint64_t s_mb[2];       // parity-buffered mbarriers
    const uint32_t allAddr = smem_u32(&s_all[0][0]);
    const uint32_t mbAddr  = smem_u32(&s_mb[0]);

    if (tid == 0) { mbar_init(mbAddr, CSZ); mbar_init(mbAddr + 8, CSZ); }

    // ---- Phase 0 finisher (redundant in all 8 CTAs): merge 74 partials/channel ----
    for (int cc = 0; cc < 2; cc++) {
        float Mk = neg_inf(), S = 0.f, Sx = 0.f, Sy = 0.f;
        if (tid < CBLK) {
            float4 p = g_p0[cc * CBLK + tid];
            Mk = p.x; S = p.y; Sx = p.z; Sy = p.w;
        }
        float Mg = block_max_bcast(Mk);
        float e = (tid < CBLK) ? expf((Mk - Mg) * 100.f) : 0.f;
        S *= e; Sx *= e; Sy *= e;
        block_sum3(S, Sx, Sy);
        if (tid == 0) {
            float ax = Sx / S, ay = Sy / S;
            s_ay2[cc] = ay;
            if (b == 0) { out[(9 + cc) * 2 + 0] = ax; out[(9 + cc) * 2 + 1] = ay; }
        }
        __syncthreads();
    }
    float yA = s_ay2[0], yB = s_ay2[1];
    float dis = __fsub_rn(yB, yA), dsum = 0.f, dnum = 0.f;

    CLUSTER_BAR();      // all mbarrier inits visible before any remote arrive

    // ---------------- Band phases i = 8 .. 0 (mbarrier push protocol) ----------------
    for (int i = 8; i >= 0; i--) {
        // scalar band logic, redundant in all threads; __f*_rn blocks FMA contraction
        {
            float tmp = ceilf(__fsub_rn(yB, yA));
            if (fabsf(__fsub_rn(tmp, dis)) > __fmul_rn(0.35f, dis)) {
                dsum = __fadd_rn(dsum, tmp);
                dnum = __fadd_rn(dnum, 1.0f);
                dis  = __fdiv_rn(dsum, fmaxf(dnum, 1.0f));
            }
        }
        float last_y = floorf(yA);
        float t  = __fmul_rn(1.8f, dis);
        float sr = __fsub_rn(last_y, t);
        float end_y   = rintf(__fadd_rn(sr, t));   // round-half-even = jnp.round
        float start_y = rintf(sr);
        const int r0 = (start_y <= 0.f) ? 0  : (start_y >= (float)HH       ? HH     : (int)start_y);
        const int r1 = (end_y   <  0.f) ? -1 : (end_y   >= (float)(HH - 1) ? HH - 1 : (int)end_y);
        const int rows = r1 - r0 + 1;
        const int nelt = rows * 512;                // float4 count (<=0 if empty)
        const int j    = 8 - i;
        const int par  = j & 1;
        const unsigned wp = (unsigned)((j >> 1) & 1);   // each mbar flips every 2nd band
        const float *chan = hm + (size_t)i * HH * WW;

        // L2 prefetch of the PREDICTED next band (window shifted up by ~dis).
        // Pure hint: misprediction just leaves next band cold, as before.
        if (i > 0 && rows > 0) {
            int d = (int)dis;
            int pr0 = r0 - d - 12; if (pr0 < 0) pr0 = 0;
            int pr1 = r1 - d + 12; if (pr1 > HH - 1) pr1 = HH - 1;
            const float *nchan = chan - (size_t)HH * WW;   // channel i-1
            int pn = (pr1 - pr0 + 1) * 512;
            for (int g = b * NT + tid; g < pn; g += CSZ * NT) {
                const float4 *pp = reinterpret_cast<const float4*>(nchan + (size_t)(pr0 + (g >> 9)) * WW) + (g & 511);
                asm volatile("prefetch.global.L2 [%0];" :: "l"(pp));
            }
        }

        float Mpub, S = 0.f, Sx = 0.f, Sy = 0.f;    // partial (M scaled)
        if (nelt <= 2 * CSZ * NT) {
            // ---- fast path (rows <= 32): <=2 reg-resident tiles/thread ----
            const int g0 = b * NT + tid, g1 = g0 + CSZ * NT;
            const bool v0 = g0 < nelt, v1 = g1 < nelt;
            float4 A0, A1;
            float tm0 = neg_inf(), tm1 = neg_inf();
            if (v0) { A0 = reinterpret_cast<const float4*>(chan + (size_t)(r0 + (g0 >> 9)) * WW)[g0 & 511]; tm0 = fmax4(A0); }
            if (v1) { A1 = reinterpret_cast<const float4*>(chan + (size_t)(r0 + (g1 >> 9)) * WW)[g1 & 511]; tm1 = fmax4(A1); }
            float Mcta = cmax2(fmaxf(tm0, tm1));    // raw CTA max (2 bars)
            const float Ms  = Mcta * 100.f;
            const float thr = Mcta - 0.88f;
            if (__any_sync(0xffffffffu, tm0 > thr)) {
                if (v0) {
                    float e0 = expf(A0.x * 100.f - Ms), e1 = expf(A0.y * 100.f - Ms);
                    float e2 = expf(A0.z * 100.f - Ms), e3 = expf(A0.w * 100.f - Ms);
                    float es = (e0 + e1) + (e2 + e3);
                    float x0 = (float)((g0 & 511) << 2);
                    S  += es;
                    Sx += x0 * e0 + (x0 + 1.f) * e1 + (x0 + 2.f) * e2 + (x0 + 3.f) * e3;
                    Sy += (float)(r0 + (g0 >> 9)) * es;
                }
            }
            if (__any_sync(0xffffffffu, tm1 > thr)) {
                if (v1) {
                    float e0 = expf(A1.x * 100.f - Ms), e1 = expf(A1.y * 100.f - Ms);
                    float e2 = expf(A1.z * 100.f - Ms), e3 = expf(A1.w * 100.f - Ms);
                    float es = (e0 + e1) + (e2 + e3);
                    float x0 = (float)((g1 & 511) << 2);
                    S  += es;
                    Sx += x0 * e0 + (x0 + 1.f) * e1 + (x0 + 2.f) * e2 + (x0 + 3.f) * e3;
                    Sy += (float)(r0 + (g1 >> 9)) * es;
                }
            }
            Mpub = Ms;                              // -inf fine for empty CTAs
        } else {
            // ---- slow path (rows > 32, rare): per-thread online, scaled domain ----
            float Mt = neg_inf();
            for (int g = b * NT + tid; g < nelt; g += CSZ * NT) {
                int row = r0 + (g >> 9);
                float4 A = reinterpret_cast<const float4*>(chan + (size_t)row * WW)[g & 511];
                float q0 = A.x * 100.f, q1 = A.y * 100.f, q2 = A.z * 100.f, q3 = A.w * 100.f;
                float mr = fmaxf(fmaxf(q0, q1), fmaxf(q2, q3));
                if (mr > Mt) {
                    float r = expf(Mt - mr);        // expf(-inf)=0 first time
                    S *= r; Sx *= r; Sy *= r;
                    Mt = mr;
                }
                float e0 = expf(q0 - Mt), e1 = expf(q1 - Mt), e2 = expf(q2 - Mt), e3 = expf(q3 - Mt);
                float es = (e0 + e1) + (e2 + e3);
                float x0 = (float)((g & 511) << 2);
                S  += es;
                Sx += x0 * e0 + (x0 + 1.f) * e1 + (x0 + 2.f) * e2 + (x0 + 3.f) * e3;
                Sy += (float)row * es;
            }
            float Msc = cmax2(Mt);                  // scaled CTA max
            float e = (Mt == neg_inf()) ? 0.f : expf(Mt - Msc);
            S *= e; Sx *= e; Sy *= e;
            Mpub = Msc;
        }

        // CTA sum reduce (1 bar); totals land in all lanes of warp 0
        #pragma unroll
        for (int o = 16; o; o >>= 1) {
            S  += __shfl_xor_sync(0xffffffffu, S, o);
            Sx += __shfl_xor_sync(0xffffffffu, Sx, o);
            Sy += __shfl_xor_sync(0xffffffffu, Sy, o);
        }
        if (lane == 0) { sRed[w][0] = S; sRed[w][1] = Sx; sRed[w][2] = Sy; }
        __syncthreads();
        if (tid < 32) {
            S = sRed[tid][0]; Sx = sRed[tid][1]; Sy = sRed[tid][2];
            #pragma unroll
            for (int o = 16; o; o >>= 1) {
                S  += __shfl_xor_sync(0xffffffffu, S, o);
                Sx += __shfl_xor_sync(0xffffffffu, Sx, o);
                Sy += __shfl_xor_sync(0xffffffffu, Sy, o);
            }
            // push my partial into EVERY peer's s_all[par][b] + arrive on their mbar[par]
            if (tid < CSZ) {
                uint32_t dst = mapa_u32(allAddr + (uint32_t)((par * CSZ + b) * 16), (uint32_t)tid);
                st_clu_b64(dst,     pack2(Mpub, S));
                st_clu_b64(dst + 8, pack2(Sx, Sy));
                mbar_arrive_remote(mapa_u32(mbAddr + (uint32_t)(par * 8), (uint32_t)tid));
            }
            // wait for all 8 pushes on my LOCAL mbar, then fold from LOCAL smem
            mbar_wait(mbAddr + (uint32_t)(par * 8), wp);
            float Mk = neg_inf(), T = 0.f, Tx = 0.f, Ty = 0.f;
            if (tid < CSZ) {
                float4 p = s_all[par][tid];
                Mk = p.x; T = p.y; Tx = p.z; Ty = p.w;
            }
            float Mg = Mk;
            #pragma unroll
            for (int o = 16; o; o >>= 1) Mg = fmaxf(Mg, __shfl_xor_sync(0xffffffffu, Mg, o));
            float e2 = (Mk == neg_inf()) ? 0.f : expf(Mk - Mg);
            T *= e2; Tx *= e2; Ty *= e2;
            #pragma unroll
            for (int o = 16; o; o >>= 1) {
                T  += __shfl_xor_sync(0xffffffffu, T, o);
                Tx += __shfl_xor_sync(0xffffffffu, Tx, o);
                Ty += __shfl_xor_sync(0xffffffffu, Ty, o);
            }
            if (tid == 0) {
                float Rn = (rows > 0) ? (float)rows : 0.f;
                float m;
                if (Rn >= 2048.f)      m = Mg;               // band covers everything
                else if (Rn > 0.f)     m = fmaxf(Mg, 0.f);   // zeros exist outside band
                else                   m = 0.f;              // empty band: all-zero map
                float sc = (Rn > 0.f) ? expf(Mg - m) : 0.f;
                T *= sc; Tx *= sc; Ty *= sc;
                if (Rn < 2048.f) {
                    const float NTOT  = 4194304.f;      // H*W
                    const float SXROW = 2096128.f;      // W*(W-1)/2
                    const float SXTOT = 4292870144.f;   // H * SXROW
                    const float SYTOT = 4292870144.f;   // W * H*(H-1)/2
                    float e0 = expf(-m);
                    T  += (NTOT  - Rn * 2048.f) * e0;
                    Tx += (SXTOT - Rn * SXROW ) * e0;
                    Ty += (SYTOT - 2048.f * (0.5f * (float)(r0 + r1) * Rn)) * e0;
                }
                float ax = Tx / T, ay = Ty / T;
                s_ay = ay;
                if (b == 0) { out[i * 2 + 0] = ax; out[i * 2 + 1] = ay; }
            }
        }
        __syncthreads();
        yB = yA;
        yA = s_ay;
    }

    // quiesce cluster before smem teardown
    CLUSTER_BAR();
    if (tid == 0) { mbar_inval(mbAddr); mbar_inval(mbAddr + 8); }
}

extern "C" void kernel_launch(void* const* d_in, const int* in_sizes, int n_in,
                              void* d_out, int out_size) {
    const float *hm = (const float*)d_in[0];
    float *out = (float*)d_out;
    (void)in_sizes; (void)n_in; (void)out_size;

    phase0_kernel<<<NB, NT>>>(hm);
    bands_kernel<<<CSZ, NT>>>(hm, out);
}

// round 14
// speedup vs baseline: 1.3962x; 1.3962x over previous
#include <cuda_runtime.h>
#include <cstdint>

#define HH 2048
#define WW 2048
#define NB 148
#define NT 1024
#define NW 32
#define CBLK 74
#define TOT4 (HH*WW/4)          // 1,048,576 float4 per channel
#define STR (CBLK*NT)           // 75,776
#define TMAX 16                 // per-thread tile maxima kept in regs (rows <= 32)

// Only cross-kernel state: phase-0 block partials, fully rewritten each launch.
__device__ float4 g_p0[NB];

__device__ __forceinline__ float neg_inf() { return __int_as_float(0xff800000); }
__device__ __forceinline__ float fmax4(float4 A) {
    return fmaxf(fmaxf(A.x, A.y), fmaxf(A.z, A.w));
}

// Block-wide max, broadcast to ALL threads.
__device__ float block_max_bcast(float m) {
    __shared__ float sm[NW];
    __shared__ float sM;
    int tid = threadIdx.x;
    __syncthreads();
    #pragma unroll
    for (int o = 16; o; o >>= 1) m = fmaxf(m, __shfl_xor_sync(0xffffffffu, m, o));
    if ((tid & 31) == 0) sm[tid >> 5] = m;
    __syncthreads();
    if (tid < 32) {
        float t = sm[tid];
        #pragma unroll
        for (int o = 16; o; o >>= 1) t = fmaxf(t, __shfl_xor_sync(0xffffffffu, t, o));
        if (tid == 0) sM = t;
    }
    __syncthreads();
    return sM;
}

// Block-wide 3-way sum; result valid on threads 0..31.
__device__ void block_sum3(float &S, float &Sx, float &Sy) {
    __shared__ float ss[NW][3];
    int tid = threadIdx.x;
    __syncthreads();
    #pragma unroll
    for (int o = 16; o; o >>= 1) {
        S  += __shfl_xor_sync(0xffffffffu, S, o);
        Sx += __shfl_xor_sync(0xffffffffu, Sx, o);
        Sy += __shfl_xor_sync(0xffffffffu, Sy, o);
    }
    if ((tid & 31) == 0) { ss[tid >> 5][0] = S; ss[tid >> 5][1] = Sx; ss[tid >> 5][2] = Sy; }
    __syncthreads();
    if (tid < 32) {
        S = ss[tid][0]; Sx = ss[tid][1]; Sy = ss[tid][2];
        #pragma unroll
        for (int o = 16; o; o >>= 1) {
            S  += __shfl_xor_sync(0xffffffffu, S, o);
            Sx += __shfl_xor_sync(0xffffffffu, Sx, o);
            Sy += __shfl_xor_sync(0xffffffffu, Sy, o);
        }
    }
}

// Fixed-max accumulate (phase0 reload). Ms is the SCALED (x100) block max.
__device__ __forceinline__ void accf(float Ms, float &S, float &Sx, float &Sy,
                                     float raw, float x, float y) {
    float v = raw * 100.f;
    if (v > Ms - 88.f) {
        float e = expf(v - Ms);
        S += e; Sx += x * e; Sy += y * e;
    }
}

// ================= Kernel A: phase-0 streaming (148 blocks, no sync) =================
__global__ void __launch_bounds__(NT, 1)
phase0_kernel(const float * __restrict__ hm) {
    const int b = blockIdx.x;
    const int tid = threadIdx.x;
    const int c  = (b < CBLK) ? 0 : 1;
    const int bb = (b < CBLK) ? b : b - CBLK;
    const float4 *p4 = reinterpret_cast<const float4*>(hm + (size_t)(9 + c) * HH * WW);
    const int ibase = bb * NT + tid;

    // pass A: branch-free RAW max, tile maxima kept in regs
    float bmx[4];
    #pragma unroll
    for (int k = 0; k < 3; k++) {
        float4 A = p4[ibase + (4*k + 0) * STR];
        float4 B = p4[ibase + (4*k + 1) * STR];
        float4 C = p4[ibase + (4*k + 2) * STR];
        float4 D = p4[ibase + (4*k + 3) * STR];
        bmx[k] = fmaxf(fmaxf(fmax4(A), fmax4(B)), fmaxf(fmax4(C), fmax4(D)));
    }
    {
        float4 A = p4[ibase + 12 * STR];
        float m3 = fmax4(A);
        int i13 = ibase + 13 * STR;
        if (i13 < TOT4) { float4 B = p4[i13]; m3 = fmaxf(m3, fmax4(B)); }
        bmx[3] = m3;
    }
    float Mb = block_max_bcast(fmaxf(fmaxf(bmx[0], bmx[1]), fmaxf(bmx[2], bmx[3])));

    // pass B: ballot-skip reload of qualifying tiles (L2 hits), sums rel. BLOCK max
    const float Ms     = Mb * 100.f;
    const float thrRaw = Mb - 0.88f;
    float S = 0.f, Sx = 0.f, Sy = 0.f;
    #pragma unroll
    for (int k = 0; k < 4; k++) {
        if (__any_sync(0xffffffffu, bmx[k] > thrRaw)) {
            int tlo = 4 * k, thi = (k == 3) ? 14 : 4 * k + 4;
            for (int t = tlo; t < thi; t++) {
                int idx = ibase + t * STR;
                if (idx < TOT4) {
                    float4 A = p4[idx];
                    float y  = (float)(idx >> 9);
                    float x0 = (float)((idx & 511) << 2);
                    accf(Ms, S, Sx, Sy, A.x, x0,       y);
                    accf(Ms, S, Sx, Sy, A.y, x0 + 1.f, y);
                    accf(Ms, S, Sx, Sy, A.z, x0 + 2.f, y);
                    accf(Ms, S, Sx, Sy, A.w, x0 + 3.f, y);
                }
            }
        }
    }
    block_sum3(S, Sx, Sy);
    if (tid == 0) g_p0[b] = make_float4(Mb, S, Sx, Sy);   // RAW max + relative sums
}

// ============ Kernel B: finisher + 9 band phases, ONE CTA (no inter-CTA sync) ============
__global__ void __launch_bounds__(NT, 1)
bands_kernel(const float * __restrict__ hm, float * __restrict__ out) {
    const int tid = threadIdx.x;
    const int lane = tid & 31;
    const int w = tid >> 5;
    __shared__ float s_ay, s_ay2[2];
    __shared__ float4 sP[NW];           // per-warp band partials (M scaled, S, Sx, Sy)

    // ---- Phase 0 finisher: merge 74 partials per channel ----
    for (int cc = 0; cc < 2; cc++) {
        float Mk = neg_inf(), S = 0.f, Sx = 0.f, Sy = 0.f;
        if (tid < CBLK) {
            float4 p = g_p0[cc * CBLK + tid];
            Mk = p.x; S = p.y; Sx = p.z; Sy = p.w;
        }
        float Mg = block_max_bcast(Mk);
        float e = (tid < CBLK) ? expf((Mk - Mg) * 100.f) : 0.f;
        S *= e; Sx *= e; Sy *= e;
        block_sum3(S, Sx, Sy);
        if (tid == 0) {
            float ax = Sx / S, ay = Sy / S;
            s_ay2[cc] = ay;
            out[(9 + cc) * 2 + 0] = ax; out[(9 + cc) * 2 + 1] = ay;
        }
        __syncthreads();
    }
    float yA = s_ay2[0], yB = s_ay2[1];
    float dis = __fsub_rn(yB, yA), dsum = 0.f, dnum = 0.f;

    // ---------------- Band phases i = 8 .. 0 (2 block bars each) ----------------
    for (int i = 8; i >= 0; i--) {
        // scalar band logic, redundant in all threads; __f*_rn blocks FMA contraction
        {
            float tmp = ceilf(__fsub_rn(yB, yA));
            if (fabsf(__fsub_rn(tmp, dis)) > __fmul_rn(0.35f, dis)) {
                dsum = __fadd_rn(dsum, tmp);
                dnum = __fadd_rn(dnum, 1.0f);
                dis  = __fdiv_rn(dsum, fmaxf(dnum, 1.0f));
            }
        }
        float last_y = floorf(yA);
        float t  = __fmul_rn(1.8f, dis);
        float sr = __fsub_rn(last_y, t);
        float end_y   = rintf(__fadd_rn(sr, t));   // round-half-even = jnp.round
        float start_y = rintf(sr);
        const int r0 = (start_y <= 0.f) ? 0  : (start_y >= (float)HH       ? HH     : (int)start_y);
        const int r1 = (end_y   <  0.f) ? -1 : (end_y   >= (float)(HH - 1) ? HH - 1 : (int)end_y);
        const int rows = r1 - r0 + 1;
        const int nelt = rows * 512;                // float4 count (<=0 if empty)
        const int Tn   = (nelt + NT - 1) / NT;      // tiles per thread (strided)
        const float *chan = hm + (size_t)i * HH * WW;

        float wmr = neg_inf();                      // raw warp max
        float S = 0.f, Sx = 0.f, Sy = 0.f;

        if (Tn <= TMAX) {
            // ---- fast path: per-tile maxima kept in registers ----
            float tm[TMAX];
            for (int tt = 0; tt < Tn; tt++) {
                int g = tt * NT + tid;
                float mv = neg_inf();
                if (g < nelt) {
                    float4 A = reinterpret_cast<const float4*>(chan + (size_t)(r0 + (g >> 9)) * WW)[g & 511];
                    mv = fmax4(A);
                }
                tm[tt] = mv;
                wmr = fmaxf(wmr, mv);
            }
            #pragma unroll
            for (int o = 16; o; o >>= 1) wmr = fmaxf(wmr, __shfl_xor_sync(0xffffffffu, wmr, o));
            const float Ms  = wmr * 100.f;
            const float thr = wmr - 0.88f;
            for (int tt = 0; tt < Tn; tt++) {
                if (__any_sync(0xffffffffu, tm[tt] > thr)) {
                    int g = tt * NT + tid;
                    if (g < nelt) {
                        float4 A = reinterpret_cast<const float4*>(chan + (size_t)(r0 + (g >> 9)) * WW)[g & 511];
                        float e0 = expf(A.x * 100.f - Ms), e1 = expf(A.y * 100.f - Ms);
                        float e2 = expf(A.z * 100.f - Ms), e3 = expf(A.w * 100.f - Ms);
                        float es = (e0 + e1) + (e2 + e3);
                        float x0 = (float)((g & 511) << 2);
                        S  += es;
                        Sx += x0 * e0 + (x0 + 1.f) * e1 + (x0 + 2.f) * e2 + (x0 + 3.f) * e3;
                        Sy += (float)(r0 + (g >> 9)) * es;
                    }
                }
            }
        } else {
            // ---- slow path (wide band): max pass + full reload with on-the-fly ballot ----
            for (int tt = 0; tt < Tn; tt++) {
                int g = tt * NT + tid;
                if (g < nelt) {
                    float4 A = reinterpret_cast<const float4*>(chan + (size_t)(r0 + (g >> 9)) * WW)[g & 511];
                    wmr = fmaxf(wmr, fmax4(A));
                }
            }
            #pragma unroll
            for (int o = 16; o; o >>= 1) wmr = fmaxf(wmr, __shfl_xor_sync(0xffffffffu, wmr, o));
            const float Ms  = wmr * 100.f;
            const float thr = wmr - 0.88f;
            for (int tt = 0; tt < Tn; tt++) {
                int g = tt * NT + tid;
                bool v = g < nelt;
                float4 A;
                float mv = neg_inf();
                if (v) {
                    A = reinterpret_cast<const float4*>(chan + (size_t)(r0 + (g >> 9)) * WW)[g & 511];
                    mv = fmax4(A);
                }
                if (__any_sync(0xffffffffu, mv > thr)) {
                    if (v) {
                        float e0 = expf(A.x * 100.f - Ms), e1 = expf(A.y * 100.f - Ms);
                        float e2 = expf(A.z * 100.f - Ms), e3 = expf(A.w * 100.f - Ms);
                        float es = (e0 + e1) + (e2 + e3);
                        float x0 = (float)((g & 511) << 2);
                        S  += es;
                        Sx += x0 * e0 + (x0 + 1.f) * e1 + (x0 + 2.f) * e2 + (x0 + 3.f) * e3;
                        Sy += (float)(r0 + (g >> 9)) * es;
                    }
                }
            }
        }

        // warp partial: sums relative to warp max (no bar yet)
        #pragma unroll
        for (int o = 16; o; o >>= 1) {
            S  += __shfl_xor_sync(0xffffffffu, S, o);
            Sx += __shfl_xor_sync(0xffffffffu, Sx, o);
            Sy += __shfl_xor_sync(0xffffffffu, Sy, o);
        }
        if (lane == 0) sP[w] = make_float4(wmr * 100.f, S, Sx, Sy);   // M scaled; -inf if empty
        __syncthreads();                    // BAR A

        if (tid < 32) {
            // fold 32 warp partials (two-step logsumexp) + closed-form tail
            float4 p = sP[tid];
            float Mk = p.x, T = p.y, Tx = p.z, Ty = p.w;
            float Mg = Mk;
            #pragma unroll
            for (int o = 16; o; o >>= 1) Mg = fmaxf(Mg, __shfl_xor_sync(0xffffffffu, Mg, o));
            float e2 = (Mk == neg_inf()) ? 0.f : expf(Mk - Mg);
            T *= e2; Tx *= e2; Ty *= e2;
            #pragma unroll
            for (int o = 16; o; o >>= 1) {
                T  += __shfl_xor_sync(0xffffffffu, T, o);
                Tx += __shfl_xor_sync(0xffffffffu, Tx, o);
                Ty += __shfl_xor_sync(0xffffffffu, Ty, o);
            }
            if (tid == 0) {
                float Rn = (rows > 0) ? (float)rows : 0.f;
                float m;
                if (Rn >= 2048.f)      m = Mg;               // band covers everything
                else if (Rn > 0.f)     m = fmaxf(Mg, 0.f);   // zeros exist outside band
                else                   m = 0.f;              // empty band: all-zero map
                float sc = (Rn > 0.f) ? expf(Mg - m) : 0.f;
                T *= sc; Tx *= sc; Ty *= sc;
                if (Rn < 2048.f) {
                    const float NTOT  = 4194304.f;      // H*W
                    const float SXROW = 2096128.f;      // W*(W-1)/2
                    const float SXTOT = 4292870144.f;   // H * SXROW
                    const float SYTOT = 4292870144.f;   // W * H*(H-1)/2
                    float e0 = expf(-m);
                    T  += (NTOT  - Rn * 2048.f) * e0;
                    Tx += (SXTOT - Rn * SXROW ) * e0;
                    Ty += (SYTOT - 2048.f * (0.5f * (float)(r0 + r1) * Rn)) * e0;
                }
                float ax = Tx / T, ay = Ty / T;
                s_ay = ay;
                out[i * 2 + 0] = ax; out[i * 2 + 1] = ay;
            }
        }
        __syncthreads();                    // BAR B
        yB = yA;
        yA = s_ay;
    }
}

extern "C" void kernel_launch(void* const* d_in, const int* in_sizes, int n_in,
                              void* d_out, int out_size) {
    const float *hm = (const float*)d_in[0];
    float *out = (float*)d_out;
    (void)in_sizes; (void)n_in; (void)out_size;

    phase0_kernel<<<NB, NT>>>(hm);
    bands_kernel<<<1, NT>>>(hm, out);
}

// round 16
// speedup vs baseline: 1.4087x; 1.0089x over previous
#include <cuda_runtime.h>
#include <cstdint>

#define HH 2048
#define WW 2048
#define NB 148
#define NT 1024
#define NW 32
#define CBLK 74
#define TOT4 (HH*WW/4)          // 1,048,576 float4 per channel
#define STR (CBLK*NT)           // 75,776
#define TMAX 16                 // per-thread tile maxima kept in regs (rows <= 32)

// Only cross-kernel state: phase-0 block partials, fully rewritten each launch.
__device__ float4 g_p0[NB];

__device__ __forceinline__ float neg_inf() { return __int_as_float(0xff800000); }
__device__ __forceinline__ float fmax4(float4 A) {
    return fmaxf(fmaxf(A.x, A.y), fmaxf(A.z, A.w));
}

// Block-wide max, broadcast to ALL threads.
__device__ float block_max_bcast(float m) {
    __shared__ float sm[NW];
    __shared__ float sM;
    int tid = threadIdx.x;
    __syncthreads();
    #pragma unroll
    for (int o = 16; o; o >>= 1) m = fmaxf(m, __shfl_xor_sync(0xffffffffu, m, o));
    if ((tid & 31) == 0) sm[tid >> 5] = m;
    __syncthreads();
    if (tid < 32) {
        float t = sm[tid];
        #pragma unroll
        for (int o = 16; o; o >>= 1) t = fmaxf(t, __shfl_xor_sync(0xffffffffu, t, o));
        if (tid == 0) sM = t;
    }
    __syncthreads();
    return sM;
}

// Block-wide 3-way sum; result valid on threads 0..31.
__device__ void block_sum3(float &S, float &Sx, float &Sy) {
    __shared__ float ss[NW][3];
    int tid = threadIdx.x;
    __syncthreads();
    #pragma unroll
    for (int o = 16; o; o >>= 1) {
        S  += __shfl_xor_sync(0xffffffffu, S, o);
        Sx += __shfl_xor_sync(0xffffffffu, Sx, o);
        Sy += __shfl_xor_sync(0xffffffffu, Sy, o);
    }
    if ((tid & 31) == 0) { ss[tid >> 5][0] = S; ss[tid >> 5][1] = Sx; ss[tid >> 5][2] = Sy; }
    __syncthreads();
    if (tid < 32) {
        S = ss[tid][0]; Sx = ss[tid][1]; Sy = ss[tid][2];
        #pragma unroll
        for (int o = 16; o; o >>= 1) {
            S  += __shfl_xor_sync(0xffffffffu, S, o);
            Sx += __shfl_xor_sync(0xffffffffu, Sx, o);
            Sy += __shfl_xor_sync(0xffffffffu, Sy, o);
        }
    }
}

// Fixed-max accumulate (phase0 reload). Ms is the SCALED (x100) block max.
__device__ __forceinline__ void accf(float Ms, float &S, float &Sx, float &Sy,
                                     float raw, float x, float y) {
    float v = raw * 100.f;
    if (v > Ms - 88.f) {
        float e = expf(v - Ms);
        S += e; Sx += x * e; Sy += y * e;
    }
}

// ================= Kernel A: phase-0 streaming (148 blocks, no sync) =================
__global__ void __launch_bounds__(NT, 1)
phase0_kernel(const float * __restrict__ hm) {
    const int b = blockIdx.x;
    const int tid = threadIdx.x;
    const int c  = (b < CBLK) ? 0 : 1;
    const int bb = (b < CBLK) ? b : b - CBLK;
    const float4 *p4 = reinterpret_cast<const float4*>(hm + (size_t)(9 + c) * HH * WW);
    const int ibase = bb * NT + tid;

    // pass A: branch-free RAW max, 8/6 loads batched for MLP; two 7-tile groups
    float bmx[2];
    {
        // batch 1: tiles 0..7 (8 independent LDG.128 in flight)
        float4 T0 = p4[ibase + 0 * STR];
        float4 T1 = p4[ibase + 1 * STR];
        float4 T2 = p4[ibase + 2 * STR];
        float4 T3 = p4[ibase + 3 * STR];
        float4 T4 = p4[ibase + 4 * STR];
        float4 T5 = p4[ibase + 5 * STR];
        float4 T6 = p4[ibase + 6 * STR];
        float4 T7 = p4[ibase + 7 * STR];
        float m0 = fmaxf(fmaxf(fmax4(T0), fmax4(T1)), fmaxf(fmax4(T2), fmax4(T3)));
        float m1 = fmaxf(fmax4(T4), fmaxf(fmax4(T5), fmax4(T6)));
        bmx[0] = fmaxf(m0, m1);                    // group 0 = tiles 0..6
        // batch 2: tiles 8..13 (6 loads; tile 13 predicated)
        float4 U0 = p4[ibase + 8 * STR];
        float4 U1 = p4[ibase + 9 * STR];
        float4 U2 = p4[ibase + 10 * STR];
        float4 U3 = p4[ibase + 11 * STR];
        float4 U4 = p4[ibase + 12 * STR];
        int i13 = ibase + 13 * STR;
        float m13 = neg_inf();
        if (i13 < TOT4) { float4 U5 = p4[i13]; m13 = fmax4(U5); }
        float m2 = fmaxf(fmaxf(fmax4(U0), fmax4(U1)), fmaxf(fmax4(U2), fmax4(U3)));
        bmx[1] = fmaxf(fmaxf(fmax4(T7), m13), fmaxf(m2, fmax4(U4)));   // group 1 = tiles 7..13
    }
    float Mb = block_max_bcast(fmaxf(bmx[0], bmx[1]));

    // pass B: ballot-skip reload of qualifying 7-tile groups (L2 hits), sums rel. BLOCK max
    const float Ms     = Mb * 100.f;
    const float thrRaw = Mb - 0.88f;
    float S = 0.f, Sx = 0.f, Sy = 0.f;
    #pragma unroll
    for (int k = 0; k < 2; k++) {
        if (__any_sync(0xffffffffu, bmx[k] > thrRaw)) {
            int tlo = 7 * k, thi = 7 * k + 7;
            for (int t = tlo; t < thi; t++) {
                int idx = ibase + t * STR;
                if (idx < TOT4) {
                    float4 A = p4[idx];
                    float y  = (float)(idx >> 9);
                    float x0 = (float)((idx & 511) << 2);
                    accf(Ms, S, Sx, Sy, A.x, x0,       y);
                    accf(Ms, S, Sx, Sy, A.y, x0 + 1.f, y);
                    accf(Ms, S, Sx, Sy, A.z, x0 + 2.f, y);
                    accf(Ms, S, Sx, Sy, A.w, x0 + 3.f, y);
                }
            }
        }
    }
    block_sum3(S, Sx, Sy);
    if (tid == 0) g_p0[b] = make_float4(Mb, S, Sx, Sy);   // RAW max + relative sums
}

// ============ Kernel B: finisher + 9 band phases, ONE CTA (no inter-CTA sync) ============
__global__ void __launch_bounds__(NT, 1)
bands_kernel(const float * __restrict__ hm, float * __restrict__ out) {
    const int tid = threadIdx.x;
    const int lane = tid & 31;
    const int w = tid >> 5;
    __shared__ float s_ay, s_ay2[2];
    __shared__ float4 sP[NW];           // per-warp band partials (M scaled, S, Sx, Sy)

    // ---- Phase 0 finisher: merge 74 partials per channel ----
    for (int cc = 0; cc < 2; cc++) {
        float Mk = neg_inf(), S = 0.f, Sx = 0.f, Sy = 0.f;
        if (tid < CBLK) {
            float4 p = g_p0[cc * CBLK + tid];
            Mk = p.x; S = p.y; Sx = p.z; Sy = p.w;
        }
        float Mg = block_max_bcast(Mk);
        float e = (tid < CBLK) ? expf((Mk - Mg) * 100.f) : 0.f;
        S *= e; Sx *= e; Sy *= e;
        block_sum3(S, Sx, Sy);
        if (tid == 0) {
            float ax = Sx / S, ay = Sy / S;
            s_ay2[cc] = ay;
            out[(9 + cc) * 2 + 0] = ax; out[(9 + cc) * 2 + 1] = ay;
        }
        __syncthreads();
    }
    float yA = s_ay2[0], yB = s_ay2[1];
    float dis = __fsub_rn(yB, yA), dsum = 0.f, dnum = 0.f;

    // per-thread constants for band addressing: column fixed, row advances by 2/tile
    const int xq  = tid & 511;          // float4 column
    const int rof = tid >> 9;           // 0 or 1
    const float x0c = (float)(xq << 2);

    // ---------------- Band phases i = 8 .. 0 (2 block bars each) ----------------
    for (int i = 8; i >= 0; i--) {
        // scalar band logic, redundant in all threads; __f*_rn blocks FMA contraction
        {
            float tmp = ceilf(__fsub_rn(yB, yA));
            if (fabsf(__fsub_rn(tmp, dis)) > __fmul_rn(0.35f, dis)) {
                dsum = __fadd_rn(dsum, tmp);
                dnum = __fadd_rn(dnum, 1.0f);
                dis  = __fdiv_rn(dsum, fmaxf(dnum, 1.0f));
            }
        }
        float last_y = floorf(yA);
        float t  = __fmul_rn(1.8f, dis);
        float sr = __fsub_rn(last_y, t);
        float end_y   = rintf(__fadd_rn(sr, t));   // round-half-even = jnp.round
        float start_y = rintf(sr);
        const int r0 = (start_y <= 0.f) ? 0  : (start_y >= (float)HH       ? HH     : (int)start_y);
        const int r1 = (end_y   <  0.f) ? -1 : (end_y   >= (float)(HH - 1) ? HH - 1 : (int)end_y);
        const int rows = r1 - r0 + 1;
        const int nelt = rows * 512;                // float4 count (<=0 if empty)
        const int Tn   = (nelt + NT - 1) / NT;      // tiles per thread (= ceil(rows/2))
        const float *chan = hm + (size_t)i * HH * WW;

        float wmr = neg_inf();                      // raw warp max
        float S = 0.f, Sx = 0.f, Sy = 0.f;

        if (Tn <= TMAX) {
            // ---- fast path: strength-reduced addressing, tile maxima in regs ----
            const float4 *fp = reinterpret_cast<const float4*>(chan + (size_t)(r0 + rof) * WW) + xq;
            float tm[TMAX];
            #pragma unroll 4
            for (int tt = 0; tt < Tn; tt++) {
                int row = r0 + rof + 2 * tt;
                float mv = neg_inf();
                if (row <= r1) mv = fmax4(fp[tt * 1024]);
                tm[tt] = mv;
                wmr = fmaxf(wmr, mv);
            }
            #pragma unroll
            for (int o = 16; o; o >>= 1) wmr = fmaxf(wmr, __shfl_xor_sync(0xffffffffu, wmr, o));
            const float Ms  = wmr * 100.f;
            const float thr = wmr - 0.88f;
            for (int tt = 0; tt < Tn; tt++) {
                if (__any_sync(0xffffffffu, tm[tt] > thr)) {
                    int row = r0 + rof + 2 * tt;
                    if (row <= r1) {
                        float4 A = fp[tt * 1024];
                        float e0 = expf(A.x * 100.f - Ms), e1 = expf(A.y * 100.f - Ms);
                        float e2 = expf(A.z * 100.f - Ms), e3 = expf(A.w * 100.f - Ms);
                        float es = (e0 + e1) + (e2 + e3);
                        S  += es;
                        Sx += x0c * e0 + (x0c + 1.f) * e1 + (x0c + 2.f) * e2 + (x0c + 3.f) * e3;
                        Sy += (float)row * es;
                    }
                }
            }
        } else {
            // ---- slow path (wide band): max pass + full reload with on-the-fly ballot ----
            #pragma unroll 4
            for (int tt = 0; tt < Tn; tt++) {
                int g = tt * NT + tid;
                if (g < nelt) {
                    float4 A = reinterpret_cast<const float4*>(chan + (size_t)(r0 + (g >> 9)) * WW)[g & 511];
                    wmr = fmaxf(wmr, fmax4(A));
                }
            }
            #pragma unroll
            for (int o = 16; o; o >>= 1) wmr = fmaxf(wmr, __shfl_xor_sync(0xffffffffu, wmr, o));
            const float Ms  = wmr * 100.f;
            const float thr = wmr - 0.88f;
            for (int tt = 0; tt < Tn; tt++) {
                int g = tt * NT + tid;
                bool v = g < nelt;
                float4 A;
                float mv = neg_inf();
                if (v) {
                    A = reinterpret_cast<const float4*>(chan + (size_t)(r0 + (g >> 9)) * WW)[g & 511];
                    mv = fmax4(A);
                }
                if (__any_sync(0xffffffffu, mv > thr)) {
                    if (v) {
                        float e0 = expf(A.x * 100.f - Ms), e1 = expf(A.y * 100.f - Ms);
                        float e2 = expf(A.z * 100.f - Ms), e3 = expf(A.w * 100.f - Ms);
                        float es = (e0 + e1) + (e2 + e3);
                        float x0 = (float)((g & 511) << 2);
                        S  += es;
                        Sx += x0 * e0 + (x0 + 1.f) * e1 + (x0 + 2.f) * e2 + (x0 + 3.f) * e3;
                        Sy += (float)(r0 + (g >> 9)) * es;
                    }
                }
            }
        }

        // warp partial: sums relative to warp max (no bar yet)
        #pragma unroll
        for (int o = 16; o; o >>= 1) {
            S  += __shfl_xor_sync(0xffffffffu, S, o);
            Sx += __shfl_xor_sync(0xffffffffu, Sx, o);
            Sy += __shfl_xor_sync(0xffffffffu, Sy, o);
        }
        if (lane == 0) sP[w] = make_float4(wmr * 100.f, S, Sx, Sy);   // M scaled; -inf if empty
        __syncthreads();                    // BAR A

        if (tid < 32) {
            // fold 32 warp partials (two-step logsumexp) + closed-form tail
            float4 p = sP[tid];
            float Mk = p.x, T = p.y, Tx = p.z, Ty = p.w;
            float Mg = Mk;
            #pragma unroll
            for (int o = 16; o; o >>= 1) Mg = fmaxf(Mg, __shfl_xor_sync(0xffffffffu, Mg, o));
            float e2 = (Mk == neg_inf()) ? 0.f : expf(Mk - Mg);
            T *= e2; Tx *= e2; Ty *= e2;
            #pragma unroll
            for (int o = 16; o; o >>= 1) {
                T  += __shfl_xor_sync(0xffffffffu, T, o);
                Tx += __shfl_xor_sync(0xffffffffu, Tx, o);
                Ty += __shfl_xor_sync(0xffffffffu, Ty, o);
            }
            if (tid == 0) {
                float Rn = (rows > 0) ? (float)rows : 0.f;
                float m;
                if (Rn >= 2048.f)      m = Mg;               // band covers everything
                else if (Rn > 0.f)     m = fmaxf(Mg, 0.f);   // zeros exist outside band
                else                   m = 0.f;              // empty band: all-zero map
                float sc = (Rn > 0.f) ? expf(Mg - m) : 0.f;
                T *= sc; Tx *= sc; Ty *= sc;
                if (Rn < 2048.f) {
                    const float NTOT  = 4194304.f;      // H*W
                    const float SXROW = 2096128.f;      // W*(W-1)/2
                    const float SXTOT = 4292870144.f;   // H * SXROW
                    const float SYTOT = 4292870144.f;   // W * H*(H-1)/2
                    float e0 = expf(-m);
                    T  += (NTOT  - Rn * 2048.f) * e0;
                    Tx += (SXTOT - Rn * SXROW ) * e0;
                    Ty += (SYTOT - 2048.f * (0.5f * (float)(r0 + r1) * Rn)) * e0;
                }
                float ax = Tx / T, ay = Ty / T;
                s_ay = ay;
                out[i * 2 + 0] = ax; out[i * 2 + 1] = ay;
            }
        }
        __syncthreads();                    // BAR B
        yB = yA;
        yA = s_ay;
    }
}

extern "C" void kernel_launch(void* const* d_in, const int* in_sizes, int n_in,
                              void* d_out, int out_size) {
    const float *hm = (const float*)d_in[0];
    float *out = (float*)d_out;
    (void)in_sizes; (void)n_in; (void)out_size;

    phase0_kernel<<<NB, NT>>>(hm);
    bands_kernel<<<1, NT>>>(hm, out);
}